// round 8
// baseline (speedup 1.0000x reference)
#include <cuda_runtime.h>
#include <stdint.h>

// Problem constants
#define TT   384      // num_thetas (= n1 = n2)
#define NN   384      // points per space
#define RR   384      // resolution
#define D1   128
#define D2   32
#define SZ1  (D1*TT)  // 49152
#define SZ2  (D2*TT)  // 12288

// Scratch (static device globals; no allocation allowed)
__device__ float g_v1[SZ1];
__device__ float g_v2[SZ2];
__device__ float g_nh1[TT*NN];   // transposed: [t][n]
__device__ float g_nh2[TT*NN];
__device__ float g_loss;
__device__ unsigned int g_done = 0;

// ---------------------------------------------------------------------------
// Threefry2x32, key = (0, 42), partitionable layout: bits(i) = o0^o1,
// counter = (0, i)
// ---------------------------------------------------------------------------
__device__ __forceinline__ uint32_t rotl32(uint32_t x, int d) {
    return (x << d) | (x >> (32 - d));
}

__device__ __forceinline__ void threefry_0_42(uint32_t x0, uint32_t x1,
                                              uint32_t& o0, uint32_t& o1) {
    const uint32_t ks0 = 0u;
    const uint32_t ks1 = 42u;
    const uint32_t ks2 = 0u ^ 42u ^ 0x1BD11BDAu;
    x0 += ks0; x1 += ks1;
#define TF_R4(a,b,c,d)                               \
    x0 += x1; x1 = rotl32(x1,(a)); x1 ^= x0;          \
    x0 += x1; x1 = rotl32(x1,(b)); x1 ^= x0;          \
    x0 += x1; x1 = rotl32(x1,(c)); x1 ^= x0;          \
    x0 += x1; x1 = rotl32(x1,(d)); x1 ^= x0;
    TF_R4(13,15,26,6)   x0 += ks1; x1 += ks2 + 1u;
    TF_R4(17,29,16,24)  x0 += ks2; x1 += ks0 + 2u;
    TF_R4(13,15,26,6)   x0 += ks0; x1 += ks1 + 3u;
    TF_R4(17,29,16,24)  x0 += ks1; x1 += ks2 + 4u;
    TF_R4(13,15,26,6)   x0 += ks2; x1 += ks0 + 5u;
#undef TF_R4
    o0 = x0; o1 = x1;
}

// XLA ErfInv float32 polynomial (log1p -> fast MUFU log; fmaf keeps 1-u^2
// accurate; direction-vector precision needs are ~1e-4)
__device__ __forceinline__ float erfinv_fast(float x) {
    float w = -__logf(fmaf(-x, x, 1.0f));
    float p;
    if (w < 5.0f) {
        w -= 2.5f;
        p = 2.81022636e-08f;
        p = fmaf(p, w, 3.43273939e-07f);
        p = fmaf(p, w, -3.5233877e-06f);
        p = fmaf(p, w, -4.39150654e-06f);
        p = fmaf(p, w, 0.00021858087f);
        p = fmaf(p, w, -0.00125372503f);
        p = fmaf(p, w, -0.00417768164f);
        p = fmaf(p, w, 0.246640727f);
        p = fmaf(p, w, 1.50140941f);
    } else {
        w = sqrtf(w) - 3.0f;
        p = -0.000200214257f;
        p = fmaf(p, w, 0.000100950558f);
        p = fmaf(p, w, 0.00134934322f);
        p = fmaf(p, w, -0.00367342844f);
        p = fmaf(p, w, 0.00573950773f);
        p = fmaf(p, w, -0.0076224613f);
        p = fmaf(p, w, 0.00943887047f);
        p = fmaf(p, w, 1.00167406f);
        p = fmaf(p, w, 2.83297682f);
    }
    return p * x;
}

__device__ __forceinline__ float bits_to_normal(uint32_t b) {
    float f = __uint_as_float((b >> 9) | 0x3F800000u) - 1.0f;   // [0,1)
    const float lo = -0.99999994f;                               // nextafter(-1,0)
    const float span = 1.0f - lo;
    float u = fmaf(f, span, lo);
    u = fmaxf(lo, u);
    return 1.41421356f * erfinv_fast(u);   // sqrt(2)
}

// ---------------------------------------------------------------------------
// 1) Generate direction matrices; resets loss accumulator for graph replay.
// ---------------------------------------------------------------------------
__global__ void gen_dirs_kernel() {
    int i = blockIdx.x * 256 + threadIdx.x;
    if (i == 0) g_loss = 0.0f;
    uint32_t idx = (i < SZ1) ? (uint32_t)i : (uint32_t)(i - SZ1);
    uint32_t o0, o1;
    threefry_0_42(0u, idx, o0, o1);
    float v = bits_to_normal(o0 ^ o1);
    if (i < SZ1)            g_v1[i] = v;
    else if (i < SZ1 + SZ2) g_v2[i - SZ1] = v;
}

// ---------------------------------------------------------------------------
// 2) nh^T[t][n] = (sum_k X[n,k] V[k,t]) * rsqrt(sum_k V[k,t]^2)
//    32x32 tile, 256 threads, 2x2 register blocking (1 LDS per FMA).
//    Column norms accumulated in registers by the V-tile loader threads.
//    blockIdx.z: 0 -> space1 (D=128), 1 -> space2 (D=32)
// ---------------------------------------------------------------------------
__global__ void __launch_bounds__(256)
gemm_kernel(const float* __restrict__ s1, const float* __restrict__ s2) {
    int space = blockIdx.z;
    const float* X = space ? s2 : s1;
    const float* V = space ? g_v2 : g_v1;
    float* OUT     = space ? g_nh2 : g_nh1;
    const int D    = space ? D2 : D1;
    const int KT   = D / 32;

    int n0 = blockIdx.x * 32;
    int t0 = blockIdx.y * 32;
    int tx = threadIdx.x;           // 0..15
    int ty = threadIdx.y;           // 0..15
    int lin = ty * 16 + tx;         // 0..255

    __shared__ float xs[32][33];    // [n][k]
    __shared__ float vs[32][33];    // [k][t]
    __shared__ float nrm[32];
    __shared__ float inv[32];

    // loader mapping (both tiles): col/k-lane = lin&31, row group = lin>>5 (0..7)
    int lcol = lin & 31;
    int lgrp = lin >> 5;

    if (lin < 32) nrm[lin] = 0.0f;

    float nsum = 0.0f;              // norm partial for column (t0 + lcol)
    float a00 = 0.0f, a01 = 0.0f, a10 = 0.0f, a11 = 0.0f;

    for (int u = 0; u < KT; u++) {
        int k0 = u * 32;
        #pragma unroll
        for (int j = 0; j < 4; j++) {
            int row = lgrp * 4 + j;
            // X tile: xs[row][lcol] -- lanes vary lcol => coalesced gmem
            xs[row][lcol] = X[(n0 + row) * D + (k0 + lcol)];
            // V tile: vs[row][lcol] = V[k0+row][t0+lcol] -- coalesced
            float v = V[(k0 + row) * TT + (t0 + lcol)];
            vs[row][lcol] = v;
            nsum = fmaf(v, v, nsum);
        }
        __syncthreads();
        #pragma unroll
        for (int k = 0; k < 32; k++) {
            float x0 = xs[tx][k];
            float x1 = xs[tx + 16][k];
            float v0 = vs[k][ty];
            float v1 = vs[k][ty + 16];
            a00 = fmaf(x0, v0, a00);
            a01 = fmaf(x0, v1, a01);
            a10 = fmaf(x1, v0, a10);
            a11 = fmaf(x1, v1, a11);
        }
        __syncthreads();
    }
    atomicAdd(&nrm[lcol], nsum);    // one atomic per thread (8 partials/col)
    __syncthreads();
    if (lin < 32) inv[lin] = rsqrtf(nrm[lin]);
    __syncthreads();

    float i0 = inv[ty], i1 = inv[ty + 16];
    OUT[(t0 + ty)      * NN + (n0 + tx)]      = a00 * i0;
    OUT[(t0 + ty + 16) * NN + (n0 + tx)]      = a01 * i1;
    OUT[(t0 + ty)      * NN + (n0 + tx + 16)] = a10 * i0;
    OUT[(t0 + ty + 16) * NN + (n0 + tx + 16)] = a11 * i1;
}

// ---------------------------------------------------------------------------
// 3) ECT difference + loss + finalize. 384 blocks x 768 threads.
//    Phase 1: every (space, point) does its step-count atomic; points whose
//    7-bin sigmoid window intersects [0,383] are ballot-compacted to smem.
//    Phase 2: only ceil(M/32) full warps run the tanh+atomic window loop.
//    sigmoid(z) = 0.5 + 0.5*tanh(z/2) via hardware tanh.approx.
// ---------------------------------------------------------------------------
__device__ __forceinline__ float tanh_hw(float x) {
    float y;
    asm("tanh.approx.f32 %0, %1;" : "=f"(y) : "f"(x));
    return y;
}

__global__ void __launch_bounds__(768) ect_loss_kernel(float* __restrict__ out) {
    int t    = blockIdx.x;
    int tid  = threadIdx.x;               // 0..767
    int lane = tid & 31, wid = tid >> 5;  // 24 warps

    __shared__ float acc[RR];
    __shared__ int   cnt[RR];
    __shared__ float sb[768];             // compacted b = -250*(1+nh)
    __shared__ int   sia[768];            // compacted (ia<<1)|neg
    __shared__ int   m_cnt;
    __shared__ int   wsum[12];
    __shared__ int   wofs[12];
    __shared__ float ps[12];

    if (tid < RR) { acc[tid] = 0.0f; cnt[tid] = 0; }
    if (tid == 0) m_cnt = 0;
    __syncthreads();

    const float AI   = 383.0f / 2.0f;     // 1/H
    const float H250 = 500.0f / 383.0f;   // (z/2) step per bin

    // NN=384 is NOT a power of two — explicit compare, no masks.
    bool  first = tid < NN;
    int   n     = first ? tid : tid - NN;
    float nh    = first ? g_nh1[t * NN + n] : g_nh2[t * NN + n];
    int   sgn   = first ? 1 : -1;

    float a  = (nh + 1.0f) * AI;
    int   ia = (int)floorf(a);

    // step part: all r >= ia+4 get the full +/-1
    int c = ia + 4; if (c < 0) c = 0;
    if (c <= RR - 1) atomicAdd(&cnt[c], sgn);

    // compact points with active windows (window [ia-3, ia+3] meets [0,RR-1])
    bool act = (ia >= -3) && (ia <= RR + 2);
    unsigned m = __ballot_sync(0xffffffffu, act);
    int base = 0;
    if (lane == 0) base = atomicAdd(&m_cnt, __popc(m));
    base = __shfl_sync(0xffffffffu, base, 0);
    if (act) {
        int idx = base + __popc(m & ((1u << lane) - 1u));
        sb[idx]  = -250.0f * (1.0f + nh);
        sia[idx] = (ia << 1) | (first ? 0 : 1);
    }
    __syncthreads();

    int M = m_cnt;
    if (tid < M) {
        float b   = sb[tid];
        int   v   = sia[tid];
        int   ia2 = v >> 1;
        float fs  = (v & 1) ? -1.0f : 1.0f;
        int   rlo = ia2 - 3;
        #pragma unroll
        for (int i = 0; i < 7; i++) {
            int r = rlo + i;
            if ((unsigned)r < (unsigned)RR) {
                float s = fmaf(0.5f, tanh_hw(fmaf((float)r, H250, b)), 0.5f);
                atomicAdd(&acc[r], fs * s);
            }
        }
    }
    __syncthreads();

    // inclusive block scan of signed cnt over r = tid (threads 0..383)
    float sq = 0.0f;
    int v = 0;
    if (tid < RR) v = cnt[tid];
    if (wid < 12) {
        #pragma unroll
        for (int o = 1; o < 32; o <<= 1) {
            int y = __shfl_up_sync(0xffffffffu, v, o);
            if (lane >= o) v += y;
        }
        if (lane == 31) wsum[wid] = v;
    }
    __syncthreads();
    if (tid < 32) {
        int a2 = (tid < 12) ? wsum[tid] : 0;
        #pragma unroll
        for (int o = 1; o < 32; o <<= 1) {
            int y = __shfl_up_sync(0xffffffffu, a2, o);
            if (tid >= o) a2 += y;
        }
        if (tid < 12) wofs[tid] = a2;
    }
    __syncthreads();
    if (tid < RR) {
        int pre = v + (wid ? wofs[wid - 1] : 0);
        float dd = acc[tid] + (float)pre;
        sq = dd * dd;
    }

    // block reduce (warps >= 12 contribute 0)
    #pragma unroll
    for (int o = 16; o; o >>= 1) sq += __shfl_down_sync(0xffffffffu, sq, o);
    if (lane == 0 && wid < 12) ps[wid] = sq;
    __syncthreads();
    if (tid == 0) {
        float s = 0.0f;
        #pragma unroll
        for (int i = 0; i < 12; i++) s += ps[i];
        atomicAdd(&g_loss, s);
        __threadfence();
        unsigned prev = atomicAdd(&g_done, 1u);
        if (prev == (unsigned)(gridDim.x - 1)) {
            g_done = 0u;  // self-reset for graph replay
            float total = *((volatile float*)&g_loss);
            out[0] = total * (1.0f / (float)(RR * TT));
        }
    }
}

extern "C" void kernel_launch(void* const* d_in, const int* in_sizes, int n_in,
                              void* d_out, int out_size) {
    const float* s1 = (const float*)d_in[0];   // [384, 128]
    const float* s2 = (const float*)d_in[1];   // [384, 32]
    float* out = (float*)d_out;

    gen_dirs_kernel<<<240, 256>>>();           // 61440 elements
    gemm_kernel<<<dim3(NN / 32, TT / 32, 2), dim3(16, 16)>>>(s1, s2);
    ect_loss_kernel<<<TT, 768>>>(out);
}

// round 9
// speedup vs baseline: 1.3384x; 1.3384x over previous
#include <cuda_runtime.h>
#include <stdint.h>

// Problem constants
#define TT   384      // num_thetas (= n1 = n2)
#define NN   384      // points per space
#define RR   384      // resolution
#define D1   128
#define D2   32
#define SZ1  (D1*TT)  // 49152
#define SZ2  (D2*TT)  // 12288

// Scratch (static device globals; no allocation allowed)
__device__ float g_v1[SZ1];
__device__ float g_v2[SZ2];
__device__ float g_nh1[TT*NN];   // transposed: [t][n]
__device__ float g_nh2[TT*NN];
__device__ float g_loss;
__device__ unsigned int g_done = 0;

// ---------------------------------------------------------------------------
// Threefry2x32, key = (0, 42), partitionable layout: bits(i) = o0^o1,
// counter = (0, i)
// ---------------------------------------------------------------------------
__device__ __forceinline__ uint32_t rotl32(uint32_t x, int d) {
    return (x << d) | (x >> (32 - d));
}

__device__ __forceinline__ void threefry_0_42(uint32_t x0, uint32_t x1,
                                              uint32_t& o0, uint32_t& o1) {
    const uint32_t ks0 = 0u;
    const uint32_t ks1 = 42u;
    const uint32_t ks2 = 0u ^ 42u ^ 0x1BD11BDAu;
    x0 += ks0; x1 += ks1;
#define TF_R4(a,b,c,d)                               \
    x0 += x1; x1 = rotl32(x1,(a)); x1 ^= x0;          \
    x0 += x1; x1 = rotl32(x1,(b)); x1 ^= x0;          \
    x0 += x1; x1 = rotl32(x1,(c)); x1 ^= x0;          \
    x0 += x1; x1 = rotl32(x1,(d)); x1 ^= x0;
    TF_R4(13,15,26,6)   x0 += ks1; x1 += ks2 + 1u;
    TF_R4(17,29,16,24)  x0 += ks2; x1 += ks0 + 2u;
    TF_R4(13,15,26,6)   x0 += ks0; x1 += ks1 + 3u;
    TF_R4(17,29,16,24)  x0 += ks1; x1 += ks2 + 4u;
    TF_R4(13,15,26,6)   x0 += ks2; x1 += ks0 + 5u;
#undef TF_R4
    o0 = x0; o1 = x1;
}

// XLA ErfInv float32 polynomial (log1p -> fast MUFU log; fmaf keeps 1-u^2
// accurate; direction-vector precision needs are ~1e-4)
__device__ __forceinline__ float erfinv_fast(float x) {
    float w = -__logf(fmaf(-x, x, 1.0f));
    float p;
    if (w < 5.0f) {
        w -= 2.5f;
        p = 2.81022636e-08f;
        p = fmaf(p, w, 3.43273939e-07f);
        p = fmaf(p, w, -3.5233877e-06f);
        p = fmaf(p, w, -4.39150654e-06f);
        p = fmaf(p, w, 0.00021858087f);
        p = fmaf(p, w, -0.00125372503f);
        p = fmaf(p, w, -0.00417768164f);
        p = fmaf(p, w, 0.246640727f);
        p = fmaf(p, w, 1.50140941f);
    } else {
        w = sqrtf(w) - 3.0f;
        p = -0.000200214257f;
        p = fmaf(p, w, 0.000100950558f);
        p = fmaf(p, w, 0.00134934322f);
        p = fmaf(p, w, -0.00367342844f);
        p = fmaf(p, w, 0.00573950773f);
        p = fmaf(p, w, -0.0076224613f);
        p = fmaf(p, w, 0.00943887047f);
        p = fmaf(p, w, 1.00167406f);
        p = fmaf(p, w, 2.83297682f);
    }
    return p * x;
}

__device__ __forceinline__ float bits_to_normal(uint32_t b) {
    float f = __uint_as_float((b >> 9) | 0x3F800000u) - 1.0f;   // [0,1)
    const float lo = -0.99999994f;                               // nextafter(-1,0)
    const float span = 1.0f - lo;
    float u = fmaf(f, span, lo);
    u = fmaxf(lo, u);
    return 1.41421356f * erfinv_fast(u);   // sqrt(2)
}

// ---------------------------------------------------------------------------
// 1) Generate direction matrices; resets loss accumulator for graph replay.
// ---------------------------------------------------------------------------
__global__ void gen_dirs_kernel() {
    int i = blockIdx.x * 256 + threadIdx.x;
    if (i == 0) g_loss = 0.0f;
    uint32_t idx = (i < SZ1) ? (uint32_t)i : (uint32_t)(i - SZ1);
    uint32_t o0, o1;
    threefry_0_42(0u, idx, o0, o1);
    float v = bits_to_normal(o0 ^ o1);
    if (i < SZ1)            g_v1[i] = v;
    else if (i < SZ1 + SZ2) g_v2[i - SZ1] = v;
}

// ---------------------------------------------------------------------------
// 2) nh^T[t][n] = (sum_k X[n,k] V[k,t]) * rsqrt(sum_k V[k,t]^2)
//    32x32 tile, 256 threads, 2x2 register blocking (1 LDS per FMA).
// ---------------------------------------------------------------------------
__global__ void __launch_bounds__(256)
gemm_kernel(const float* __restrict__ s1, const float* __restrict__ s2) {
    int space = blockIdx.z;
    const float* X = space ? s2 : s1;
    const float* V = space ? g_v2 : g_v1;
    float* OUT     = space ? g_nh2 : g_nh1;
    const int D    = space ? D2 : D1;
    const int KT   = D / 32;

    int n0 = blockIdx.x * 32;
    int t0 = blockIdx.y * 32;
    int tx = threadIdx.x;           // 0..15
    int ty = threadIdx.y;           // 0..15
    int lin = ty * 16 + tx;         // 0..255

    __shared__ float xs[32][33];    // [n][k]
    __shared__ float vs[32][33];    // [k][t]
    __shared__ float nrm[32];
    __shared__ float inv[32];

    int lcol = lin & 31;
    int lgrp = lin >> 5;

    if (lin < 32) nrm[lin] = 0.0f;
    __syncthreads();

    float nsum = 0.0f;
    float a00 = 0.0f, a01 = 0.0f, a10 = 0.0f, a11 = 0.0f;

    for (int u = 0; u < KT; u++) {
        int k0 = u * 32;
        #pragma unroll
        for (int j = 0; j < 4; j++) {
            int row = lgrp * 4 + j;
            xs[row][lcol] = X[(n0 + row) * D + (k0 + lcol)];
            float v = V[(k0 + row) * TT + (t0 + lcol)];
            vs[row][lcol] = v;
            nsum = fmaf(v, v, nsum);
        }
        __syncthreads();
        #pragma unroll
        for (int k = 0; k < 32; k++) {
            float x0 = xs[tx][k];
            float x1 = xs[tx + 16][k];
            float v0 = vs[k][ty];
            float v1 = vs[k][ty + 16];
            a00 = fmaf(x0, v0, a00);
            a01 = fmaf(x0, v1, a01);
            a10 = fmaf(x1, v0, a10);
            a11 = fmaf(x1, v1, a11);
        }
        __syncthreads();
    }
    atomicAdd(&nrm[lcol], nsum);
    __syncthreads();
    if (lin < 32) inv[lin] = rsqrtf(nrm[lin]);
    __syncthreads();

    float i0 = inv[ty], i1 = inv[ty + 16];
    OUT[(t0 + ty)      * NN + (n0 + tx)]      = a00 * i0;
    OUT[(t0 + ty + 16) * NN + (n0 + tx)]      = a01 * i1;
    OUT[(t0 + ty)      * NN + (n0 + tx + 16)] = a10 * i0;
    OUT[(t0 + ty + 16) * NN + (n0 + tx + 16)] = a11 * i1;
}

// ---------------------------------------------------------------------------
// 3) ECT difference + loss via counting-sort CSR + GATHER (no float atomics).
//    Buckets: B = 0 (ia <= -4, step-only), B = ia+4 in [1,390], B = 391
//    (ia >= 387, inert). Packed counts: space1 in high 16 bits, space2 low.
//    Bin r: step = signed prefix est[r+1]; window = CSR slots
//    [est[r+1], est[r+8]) per space (contiguous since buckets adjacent).
//    sigmoid(z) = 0.5 + 0.5*tanh(z/2) via hardware tanh.approx.
// ---------------------------------------------------------------------------
__device__ __forceinline__ float tanh_hw(float x) {
    float y;
    asm("tanh.approx.f32 %0, %1;" : "=f"(y) : "f"(x));
    return y;
}

#define ECT_THREADS 416   // 13 warps: covers 392-bucket scan
#define NB 392

__global__ void __launch_bounds__(ECT_THREADS)
ect_loss_kernel(float* __restrict__ out) {
    int t    = blockIdx.x;
    int tid  = threadIdx.x;               // 0..415
    int lane = tid & 31, wid = tid >> 5;  // 13 warps

    __shared__ unsigned pcnt[NB];         // packed bucket counts
    __shared__ unsigned est[NB + 1];      // packed exclusive starts
    __shared__ float    sval1[NN];        // CSR: b = -250*(1+nh), space1
    __shared__ float    sval2[NN];        // CSR space2
    __shared__ unsigned wsum[13];
    __shared__ unsigned wofs[13];
    __shared__ float    ps[13];

    if (tid < NB) pcnt[tid] = 0u;
    __syncthreads();

    const float AI   = 383.0f / 2.0f;     // 1/H
    const float H250 = 500.0f / 383.0f;   // (z/2) step per bin

    // Phase 1: count (packed atomic; return value = rank within bucket)
    int B1 = 0, B2 = 0;
    unsigned rk1 = 0, rk2 = 0;
    float b1 = 0.0f, b2 = 0.0f;
    if (tid < NN) {
        float nh1 = g_nh1[t * NN + tid];
        float nh2 = g_nh2[t * NN + tid];
        int ia1 = (int)floorf((nh1 + 1.0f) * AI);
        int ia2 = (int)floorf((nh2 + 1.0f) * AI);
        B1 = (ia1 <= -4) ? 0 : ((ia1 >= 387) ? 391 : ia1 + 4);
        B2 = (ia2 <= -4) ? 0 : ((ia2 >= 387) ? 391 : ia2 + 4);
        b1 = -250.0f * (1.0f + nh1);
        b2 = -250.0f * (1.0f + nh2);
        rk1 = atomicAdd(&pcnt[B1], 0x10000u) >> 16;
        rk2 = atomicAdd(&pcnt[B2], 1u) & 0xFFFFu;
    }
    __syncthreads();

    // Phase 2: exclusive scan of packed counts over NB buckets (13 warps).
    // High/low halves each sum to <= 384: no cross-field carry.
    unsigned v = (tid < NB) ? pcnt[tid] : 0u;
    unsigned iv = v;
    #pragma unroll
    for (int o = 1; o < 32; o <<= 1) {
        unsigned y = __shfl_up_sync(0xffffffffu, iv, o);
        if (lane >= o) iv += y;
    }
    if (lane == 31) wsum[wid] = iv;
    __syncthreads();
    if (tid < 32) {
        unsigned a = (tid < 13) ? wsum[tid] : 0u;
        #pragma unroll
        for (int o = 1; o < 32; o <<= 1) {
            unsigned y = __shfl_up_sync(0xffffffffu, a, o);
            if (tid >= o) a += y;
        }
        if (tid < 13) wofs[tid] = a;
    }
    __syncthreads();
    unsigned incl = iv + (wid ? wofs[wid - 1] : 0u);
    if (tid < NB) est[tid] = incl - v;          // exclusive start
    if (tid == NB - 1) est[NB] = incl;          // total
    __syncthreads();

    // Phase 3: scatter (conflict-free; slots unique)
    if (tid < NN) {
        sval1[(est[B1] >> 16) + rk1]   = b1;
        sval2[(est[B2] & 0xFFFFu) + rk2] = b2;
    }
    __syncthreads();

    // Phase 4: gather per bin r = tid (tid < 384)
    float sq = 0.0f;
    if (tid < RR) {
        unsigned eL = est[tid + 1];
        unsigned eR = est[tid + 8];
        // step part: signed count of points with ia <= r-4 (buckets <= r)
        float acc = (float)((int)(eL >> 16) - (int)(eL & 0xFFFFu));
        float rz  = (float)tid * H250;
        int j0 = (int)(eL >> 16),    j1 = (int)(eR >> 16);
        int k0 = (int)(eL & 0xFFFFu), k1 = (int)(eR & 0xFFFFu);
        for (int j = j0; j < j1; j++)
            acc += fmaf(0.5f, tanh_hw(rz + sval1[j]), 0.5f);
        for (int k = k0; k < k1; k++)
            acc -= fmaf(0.5f, tanh_hw(rz + sval2[k]), 0.5f);
        sq = acc * acc;
    }

    // block reduce (13 warps; warp 12 partial contributes its tid<384 lanes = 0)
    #pragma unroll
    for (int o = 16; o; o >>= 1) sq += __shfl_down_sync(0xffffffffu, sq, o);
    if (lane == 0) ps[wid] = sq;
    __syncthreads();
    if (tid == 0) {
        float s = 0.0f;
        #pragma unroll
        for (int i = 0; i < 13; i++) s += ps[i];
        atomicAdd(&g_loss, s);
        __threadfence();
        unsigned prev = atomicAdd(&g_done, 1u);
        if (prev == (unsigned)(gridDim.x - 1)) {
            g_done = 0u;  // self-reset for graph replay
            float total = *((volatile float*)&g_loss);
            out[0] = total * (1.0f / (float)(RR * TT));
        }
    }
}

extern "C" void kernel_launch(void* const* d_in, const int* in_sizes, int n_in,
                              void* d_out, int out_size) {
    const float* s1 = (const float*)d_in[0];   // [384, 128]
    const float* s2 = (const float*)d_in[1];   // [384, 32]
    float* out = (float*)d_out;

    gen_dirs_kernel<<<240, 256>>>();           // 61440 elements
    gemm_kernel<<<dim3(NN / 32, TT / 32, 2), dim3(16, 16)>>>(s1, s2);
    ect_loss_kernel<<<TT, ECT_THREADS>>>(out);
}